// round 11
// baseline (speedup 1.0000x reference)
#include <cuda_runtime.h>
#include <cstdint>

// Problem constants
#define N_PTS  262144
#define CHANS  96
#define KOFF   27

#define TILE_M   128
#define THREADS  512
#define A_STRIDE 100   // words; conflict-free for the mma A-fragment pattern (400B, 16B-mult)
#define W_STRIDE 104   // words; conflict-free for the mma B-fragment pattern (416B, 16B-mult)
#define STAGE_WORDS (TILE_M * A_STRIDE + CHANS * W_STRIDE)   // 22784 words per stage

// Scratch for the intermediate activation x = prelu(conv1(feats)) : [N, CH] fp32
__device__ float g_x[(size_t)N_PTS * CHANS];

// ---- async-bulk + mbarrier primitives ----
__device__ __forceinline__ void cp_bulk(uint32_t dst, const void* src, uint32_t bytes,
                                        uint32_t mbar) {
    asm volatile("cp.async.bulk.shared::cta.global.mbarrier::complete_tx::bytes "
                 "[%0], [%1], %2, [%3];"
                 :: "r"(dst), "l"(src), "r"(bytes), "r"(mbar) : "memory");
}
__device__ __forceinline__ void mbar_init(uint32_t mbar, uint32_t cnt) {
    asm volatile("mbarrier.init.shared.b64 [%0], %1;" :: "r"(mbar), "r"(cnt) : "memory");
}
__device__ __forceinline__ void mbar_arrive_tx(uint32_t mbar, uint32_t bytes) {
    asm volatile("mbarrier.arrive.expect_tx.shared.b64 _, [%0], %1;"
                 :: "r"(mbar), "r"(bytes) : "memory");
}
__device__ __forceinline__ void mbar_wait(uint32_t mbar, uint32_t parity) {
    uint32_t done;
    asm volatile("{\n\t.reg .pred p;\n\t"
                 "mbarrier.try_wait.parity.acquire.cta.shared::cta.b64 p, [%1], %2;\n\t"
                 "selp.b32 %0, 1, 0, p;\n\t}"
                 : "=r"(done) : "r"(mbar), "r"(parity) : "memory");
    while (!done) {
        asm volatile("{\n\t.reg .pred p;\n\t"
                     "mbarrier.try_wait.parity.acquire.cta.shared::cta.b64 p, [%1], %2, 0x989680;\n\t"
                     "selp.b32 %0, 1, 0, p;\n\t}"
                     : "=r"(done) : "r"(mbar), "r"(parity) : "memory");
    }
}

// Issue stage k into buffer `stage`: one 384B bulk copy per valid A row and per W row.
// Only tid < 256 participates (8 warp arrivals per stage use).
__device__ __forceinline__ void issue_stage(
    int k, int stage, int tb, int tid,
    const float* __restrict__ src, const int* __restrict__ nbr,
    const int* __restrict__ mask, const float* __restrict__ W,
    uint32_t smem_base, uint32_t* smem_generic)
{
    const uint32_t As   = smem_base + (uint32_t)stage * STAGE_WORDS * 4;
    const uint32_t Wsm  = As + TILE_M * A_STRIDE * 4;
    const uint32_t mbar = smem_base + 2u * STAGE_WORDS * 4 + (uint32_t)stage * 8;

    if (tid < TILE_M) {
        // ---- A rows: warps 0-3, one row per thread ----
        const size_t o = (size_t)k * N_PTS + tb + tid;
        const int idx  = nbr[o];
        const int m    = mask[o];
        const unsigned bal = __ballot_sync(0xffffffffu, m != 0);
        if ((tid & 31) == 0)
            mbar_arrive_tx(mbar, __popc(bal) * 384u);
        const uint32_t dst = As + (uint32_t)tid * A_STRIDE * 4;
        if (m) {
            cp_bulk(dst, src + (size_t)idx * CHANS, 384u, mbar);
        } else {
            uint4* zr = (uint4*)((char*)smem_generic +
                                 ((size_t)stage * STAGE_WORDS + (size_t)tid * A_STRIDE) * 4);
#pragma unroll
            for (int i = 0; i < 24; i++) zr[i] = make_uint4(0u, 0u, 0u, 0u);
        }
    } else {
        // ---- W rows: warps 4-7, thread 128+i -> W row i (i < 96) ----
        const int i = tid - TILE_M;
        const unsigned act = __ballot_sync(0xffffffffu, i < CHANS);
        if ((tid & 31) == 0)
            mbar_arrive_tx(mbar, __popc(act) * 384u);
        if (i < CHANS)
            cp_bulk(Wsm + (uint32_t)i * W_STRIDE * 4,
                    W + (size_t)k * CHANS * CHANS + (size_t)i * CHANS, 384u, mbar);
    }
}

// One sparse-conv layer: out = prelu( bias + sum_k mask * gather(src, idx_k) @ W_k [+ residual] )
// 16 warps: two k-half groups of 8; within each group 4 (M) x 2 (N) warp grid.
extern "C" __global__ void __launch_bounds__(THREADS, 1)
sparse_conv_kernel(const float* __restrict__ src,
                   const int* __restrict__ nbr,              // [K, N]
                   const int* __restrict__ mask,             // [K, N] bool->int32
                   const float* __restrict__ W,              // [K, CH, CH]
                   const float* __restrict__ bias,           // [CH]
                   const float* __restrict__ alpha,          // [1]
                   const float* __restrict__ residual,       // [N, CH] or nullptr
                   float* __restrict__ out)                  // [N, CH]
{
    extern __shared__ uint32_t smem[];
    const uint32_t smem_base = (uint32_t)__cvta_generic_to_shared(smem);

    const int tid  = threadIdx.x;
    const int lane = tid & 31;
    const int wid  = tid >> 5;
    const int tb   = blockIdx.x * TILE_M;

    const int half = wid >> 3;          // 0: kk 0-5, 1: kk 6-11
    const int w8   = wid & 7;
    const int row_base = (w8 & 3) * 32;
    const int col_base = (w8 >> 2) * 48;
    const int kk_lo = half * 6;

    float acc[2][6][4];
#pragma unroll
    for (int mt = 0; mt < 2; mt++)
#pragma unroll
        for (int nt = 0; nt < 6; nt++)
#pragma unroll
            for (int i = 0; i < 4; i++) acc[mt][nt][i] = 0.f;

    if (tid == 0) {
        mbar_init(smem_base + 2u * STAGE_WORDS * 4 + 0, 8);
        mbar_init(smem_base + 2u * STAGE_WORDS * 4 + 8, 8);
    }
    __syncthreads();

    // ---- prologue: start gather for k=0 ----
    if (tid < 256)
        issue_stage(0, 0, tb, tid, src, nbr, mask, W, smem_base, smem);

    for (int k = 0; k < KOFF; k++) {
        const int s = k & 1;
        if (k + 1 < KOFF && tid < 256)
            issue_stage(k + 1, s ^ 1, tb, tid, src, nbr, mask, W, smem_base, smem);

        mbar_wait(smem_base + 2u * STAGE_WORDS * 4 + (uint32_t)s * 8, (k >> 1) & 1);
        __syncthreads();   // TMA data + generic-proxy zero rows visible to all warps

        const uint32_t* As = smem + (size_t)s * STAGE_WORDS;
        const uint32_t* Ws = As + TILE_M * A_STRIDE;

#pragma unroll
        for (int kq = 0; kq < 6; kq++) {
            const int kk = kk_lo + kq;
            uint32_t bfrag[6][2];
#pragma unroll
            for (int nt = 0; nt < 6; nt++) {
                int c0 = kk * 8 + (lane & 3);
                int j  = col_base + nt * 8 + (lane >> 2);
                bfrag[nt][0] = Ws[c0 * W_STRIDE + j];
                bfrag[nt][1] = Ws[(c0 + 4) * W_STRIDE + j];
            }
#pragma unroll
            for (int mt = 0; mt < 2; mt++) {
                int r = row_base + mt * 16 + (lane >> 2);
                int c = kk * 8 + (lane & 3);
                uint32_t a0 = As[r * A_STRIDE + c];
                uint32_t a1 = As[(r + 8) * A_STRIDE + c];
                uint32_t a2 = As[r * A_STRIDE + c + 4];
                uint32_t a3 = As[(r + 8) * A_STRIDE + c + 4];
#pragma unroll
                for (int nt = 0; nt < 6; nt++) {
                    asm volatile(
                        "mma.sync.aligned.m16n8k8.row.col.f32.tf32.tf32.f32 "
                        "{%0,%1,%2,%3}, {%4,%5,%6,%7}, {%8,%9}, {%0,%1,%2,%3};"
                        : "+f"(acc[mt][nt][0]), "+f"(acc[mt][nt][1]),
                          "+f"(acc[mt][nt][2]), "+f"(acc[mt][nt][3])
                        : "r"(a0), "r"(a1), "r"(a2), "r"(a3),
                          "r"(bfrag[nt][0]), "r"(bfrag[nt][1]));
                }
            }
        }
        __syncthreads();   // all warps done reading stage s before k+2 overwrites it
    }

    // ---- k-split reduction: half-1 warps dump partials to smem (reuse stage 0) ----
    float* red = (float*)smem;   // 128 x 100-stride fp32 region (51.2 KB <= stage 0)
    if (half == 1) {
#pragma unroll
        for (int mt = 0; mt < 2; mt++) {
            int r = row_base + mt * 16 + (lane >> 2);
#pragma unroll
            for (int nt = 0; nt < 6; nt++) {
                int c = col_base + nt * 8 + (lane & 3) * 2;
                *(float2*)(red + r * A_STRIDE + c) =
                    make_float2(acc[mt][nt][0], acc[mt][nt][1]);
                *(float2*)(red + (r + 8) * A_STRIDE + c) =
                    make_float2(acc[mt][nt][2], acc[mt][nt][3]);
            }
        }
    }
    __syncthreads();

    // ---- epilogue (half-0 warps): add partial, bias (+ residual), PReLU, store ----
    if (half == 0) {
        const float a = alpha[0];
#pragma unroll
        for (int mt = 0; mt < 2; mt++) {
            int rl = row_base + mt * 16 + (lane >> 2);
            int r0 = tb + rl;
#pragma unroll
            for (int nt = 0; nt < 6; nt++) {
                int c0 = col_base + nt * 8 + (lane & 3) * 2;
                float2 p0 = *(float2*)(red + rl * A_STRIDE + c0);
                float2 p1 = *(float2*)(red + (rl + 8) * A_STRIDE + c0);
                float b0 = bias[c0], b1 = bias[c0 + 1];
                float v0 = acc[mt][nt][0] + p0.x + b0;
                float v1 = acc[mt][nt][1] + p0.y + b1;
                float v2 = acc[mt][nt][2] + p1.x + b0;
                float v3 = acc[mt][nt][3] + p1.y + b1;
                if (residual) {
                    v0 += residual[(size_t)r0 * CHANS + c0];
                    v1 += residual[(size_t)r0 * CHANS + c0 + 1];
                    v2 += residual[(size_t)(r0 + 8) * CHANS + c0];
                    v3 += residual[(size_t)(r0 + 8) * CHANS + c0 + 1];
                }
                v0 = v0 > 0.f ? v0 : a * v0;
                v1 = v1 > 0.f ? v1 : a * v1;
                v2 = v2 > 0.f ? v2 : a * v2;
                v3 = v3 > 0.f ? v3 : a * v3;
                *(float2*)(out + (size_t)r0 * CHANS + c0)       = make_float2(v0, v1);
                *(float2*)(out + (size_t)(r0 + 8) * CHANS + c0) = make_float2(v2, v3);
            }
        }
    }
}

static const int SMEM_BYTES = STAGE_WORDS * 2 * 4 + 16;   // stages + 2 mbarriers

extern "C" void kernel_launch(void* const* d_in, const int* in_sizes, int n_in,
                              void* d_out, int out_size) {
    const float* feats = (const float*)d_in[0];
    const int*   nbr   = (const int*)d_in[1];
    const int*   msk   = (const int*)d_in[2];   // bool promoted to int32 on the wire
    const float* W1    = (const float*)d_in[3];
    const float* b1    = (const float*)d_in[4];
    const float* a1    = (const float*)d_in[5];
    const float* W2    = (const float*)d_in[6];
    const float* b2    = (const float*)d_in[7];
    const float* a2    = (const float*)d_in[8];
    float*       out   = (float*)d_out;

    float* xbuf = nullptr;
    cudaGetSymbolAddress((void**)&xbuf, g_x);  // host-side query; capture-safe

    cudaFuncSetAttribute(sparse_conv_kernel,
                         cudaFuncAttributeMaxDynamicSharedMemorySize, SMEM_BYTES);

    dim3 grid(N_PTS / TILE_M);
    // layer 1: x = prelu(conv(feats, W1) + b1)
    sparse_conv_kernel<<<grid, THREADS, SMEM_BYTES>>>(
        feats, nbr, msk, W1, b1, a1, /*residual=*/nullptr, xbuf);
    // layer 2: out = prelu(conv(x, W2) + b2 + feats)
    sparse_conv_kernel<<<grid, THREADS, SMEM_BYTES>>>(
        xbuf, nbr, msk, W2, b2, a2, /*residual=*/feats, out);
}

// round 12
// speedup vs baseline: 1.0199x; 1.0199x over previous
#include <cuda_runtime.h>
#include <cstdint>

// Problem constants
#define N_PTS  262144
#define CHANS  96
#define KOFF   27

#define TILE_M   128
#define THREADS  512
#define A_STRIDE 100   // words; conflict-free for the mma A-fragment pattern
#define W_STRIDE 104   // words; conflict-free for the mma B-fragment pattern
#define W_TILE_WORDS (CHANS * W_STRIDE)                      // 9984 words = 39936 B
#define STAGE_WORDS (TILE_M * A_STRIDE + W_TILE_WORDS)       // 22784 words per stage

// Scratch: intermediate activation x = prelu(conv1(feats)) : [N, CH] fp32
__device__ float g_x[(size_t)N_PTS * CHANS];
// Pre-padded weights: [layer][k][96 rows x 104-word stride]
__device__ float g_Wpad[2][(size_t)KOFF * W_TILE_WORDS];

// ---- async primitives ----
__device__ __forceinline__ void cp16(uint32_t dst, const void* src, int sz) {
    asm volatile("cp.async.cg.shared.global [%0], [%1], 16, %2;"
                 :: "r"(dst), "l"(src), "r"(sz));
}
__device__ __forceinline__ void cp_commit() { asm volatile("cp.async.commit_group;"); }
__device__ __forceinline__ void cp_wait1()  { asm volatile("cp.async.wait_group 1;"); }

__device__ __forceinline__ void cp_bulk(uint32_t dst, const void* src, uint32_t bytes,
                                        uint32_t mbar) {
    asm volatile("cp.async.bulk.shared::cta.global.mbarrier::complete_tx::bytes "
                 "[%0], [%1], %2, [%3];"
                 :: "r"(dst), "l"(src), "r"(bytes), "r"(mbar) : "memory");
}
__device__ __forceinline__ void mbar_init(uint32_t mbar, uint32_t cnt) {
    asm volatile("mbarrier.init.shared.b64 [%0], %1;" :: "r"(mbar), "r"(cnt) : "memory");
}
__device__ __forceinline__ void mbar_arrive_tx(uint32_t mbar, uint32_t bytes) {
    asm volatile("mbarrier.arrive.expect_tx.shared.b64 _, [%0], %1;"
                 :: "r"(mbar), "r"(bytes) : "memory");
}
__device__ __forceinline__ void mbar_wait(uint32_t mbar, uint32_t parity) {
    uint32_t done;
    asm volatile("{\n\t.reg .pred p;\n\t"
                 "mbarrier.try_wait.parity.acquire.cta.shared::cta.b64 p, [%1], %2;\n\t"
                 "selp.b32 %0, 1, 0, p;\n\t}"
                 : "=r"(done) : "r"(mbar), "r"(parity) : "memory");
    while (!done) {
        asm volatile("{\n\t.reg .pred p;\n\t"
                     "mbarrier.try_wait.parity.acquire.cta.shared::cta.b64 p, [%1], %2, 0x989680;\n\t"
                     "selp.b32 %0, 1, 0, p;\n\t}"
                     : "=r"(done) : "r"(mbar), "r"(parity) : "memory");
    }
}

// ---- prep: repack W [K,96,96] -> padded [K, 96 x 104-stride], pad zeroed ----
extern "C" __global__ void pad_w_kernel(const float* __restrict__ W, int layer) {
    int i = blockIdx.x * blockDim.x + threadIdx.x;           // over K*96*104
    if (i >= KOFF * W_TILE_WORDS) return;
    int k = i / W_TILE_WORDS;
    int r = (i % W_TILE_WORDS) / W_STRIDE;
    int c = i % W_STRIDE;
    g_Wpad[layer][i] = (c < CHANS) ? W[((size_t)k * CHANS + r) * CHANS + c] : 0.f;
}

// Issue stage k: A via 16B cp.async (mask folded as zero-fill), W via ONE bulk copy.
__device__ __forceinline__ void issue_stage(
    int k, int stage, int tb, int tid,
    const float* __restrict__ src, const int* __restrict__ nbr,
    const int* __restrict__ mask, const float* __restrict__ Wpad,
    uint32_t smem_base)
{
    const uint32_t As   = smem_base + (uint32_t)stage * STAGE_WORDS * 4;
    const uint32_t Wsm  = As + TILE_M * A_STRIDE * 4;
    const uint32_t mbar = smem_base + 2u * STAGE_WORDS * 4 + (uint32_t)stage * 8;

    // ---- W: single 39936B bulk request ----
    if (tid == 0) {
        mbar_arrive_tx(mbar, (uint32_t)(W_TILE_WORDS * 4));
        cp_bulk(Wsm, Wpad + (size_t)k * W_TILE_WORDS, (uint32_t)(W_TILE_WORDS * 4), mbar);
    }

    // ---- A: row r = tid>>2, quarter (tid&3)*6 float4 chunks, 6 x 16B each ----
    const int r  = tid >> 2;
    const int q  = (tid & 3) * 6;          // starting float4-chunk within the row
    const size_t o = (size_t)k * N_PTS + tb + r;
    const int idx = nbr[o];
    const int m   = mask[o];
    const int sz  = m ? 16 : 0;            // sz=0 => 16B zero-fill (mask folding)
    const float* srow = src + (size_t)(m ? idx : 0) * CHANS + q * 4;
    uint32_t dst = As + (uint32_t)(r * A_STRIDE + q * 4) * 4;
#pragma unroll
    for (int i = 0; i < 6; i++)
        cp16(dst + i * 16, srow + i * 4, sz);
}

// One sparse-conv layer: out = prelu( bias + sum_k mask * gather(src, idx_k) @ W_k [+ residual] )
// 16 warps: two k-half groups of 8; within each group 4 (M) x 2 (N) warp grid.
extern "C" __global__ void __launch_bounds__(THREADS, 1)
sparse_conv_kernel(const float* __restrict__ src,
                   const int* __restrict__ nbr,              // [K, N]
                   const int* __restrict__ mask,             // [K, N] bool->int32
                   const float* __restrict__ Wpad,           // [K, 96 x 104] padded
                   const float* __restrict__ bias,           // [CH]
                   const float* __restrict__ alpha,          // [1]
                   const float* __restrict__ residual,       // [N, CH] or nullptr
                   float* __restrict__ out)                  // [N, CH]
{
    extern __shared__ uint32_t smem[];
    const uint32_t smem_base = (uint32_t)__cvta_generic_to_shared(smem);

    const int tid  = threadIdx.x;
    const int lane = tid & 31;
    const int wid  = tid >> 5;
    const int tb   = blockIdx.x * TILE_M;

    const int half = wid >> 3;          // 0: kk 0-5, 1: kk 6-11
    const int w8   = wid & 7;
    const int row_base = (w8 & 3) * 32;
    const int col_base = (w8 >> 2) * 48;
    const int kk_lo = half * 6;

    float acc[2][6][4];
#pragma unroll
    for (int mt = 0; mt < 2; mt++)
#pragma unroll
        for (int nt = 0; nt < 6; nt++)
#pragma unroll
            for (int i = 0; i < 4; i++) acc[mt][nt][i] = 0.f;

    if (tid == 0) {
        mbar_init(smem_base + 2u * STAGE_WORDS * 4 + 0, 1);
        mbar_init(smem_base + 2u * STAGE_WORDS * 4 + 8, 1);
    }
    __syncthreads();

    // ---- prologue: start gather for k=0 ----
    issue_stage(0, 0, tb, tid, src, nbr, mask, Wpad, smem_base);
    cp_commit();

    for (int k = 0; k < KOFF; k++) {
        const int s = k & 1;
        if (k + 1 < KOFF)
            issue_stage(k + 1, s ^ 1, tb, tid, src, nbr, mask, Wpad, smem_base);
        cp_commit();           // empty group on last iter keeps wait-count uniform
        cp_wait1();            // stage k's A copies (this thread) complete
        mbar_wait(smem_base + 2u * STAGE_WORDS * 4 + (uint32_t)s * 8, (k >> 1) & 1);
        __syncthreads();       // all threads' copies for stage k visible

        const uint32_t* As = smem + (size_t)s * STAGE_WORDS;
        const uint32_t* Ws = As + TILE_M * A_STRIDE;

#pragma unroll
        for (int kq = 0; kq < 6; kq++) {
            const int kk = kk_lo + kq;
            uint32_t bfrag[6][2];
#pragma unroll
            for (int nt = 0; nt < 6; nt++) {
                int c0 = kk * 8 + (lane & 3);
                int j  = col_base + nt * 8 + (lane >> 2);
                bfrag[nt][0] = Ws[c0 * W_STRIDE + j];
                bfrag[nt][1] = Ws[(c0 + 4) * W_STRIDE + j];
            }
#pragma unroll
            for (int mt = 0; mt < 2; mt++) {
                int r = row_base + mt * 16 + (lane >> 2);
                int c = kk * 8 + (lane & 3);
                uint32_t a0 = As[r * A_STRIDE + c];
                uint32_t a1 = As[(r + 8) * A_STRIDE + c];
                uint32_t a2 = As[r * A_STRIDE + c + 4];
                uint32_t a3 = As[(r + 8) * A_STRIDE + c + 4];
#pragma unroll
                for (int nt = 0; nt < 6; nt++) {
                    asm volatile(
                        "mma.sync.aligned.m16n8k8.row.col.f32.tf32.tf32.f32 "
                        "{%0,%1,%2,%3}, {%4,%5,%6,%7}, {%8,%9}, {%0,%1,%2,%3};"
                        : "+f"(acc[mt][nt][0]), "+f"(acc[mt][nt][1]),
                          "+f"(acc[mt][nt][2]), "+f"(acc[mt][nt][3])
                        : "r"(a0), "r"(a1), "r"(a2), "r"(a3),
                          "r"(bfrag[nt][0]), "r"(bfrag[nt][1]));
                }
            }
        }
        __syncthreads();   // all warps done reading stage s before k+2 overwrites it
    }

    // ---- k-split reduction: half-1 warps dump partials to smem (reuse stage 0) ----
    float* red = (float*)smem;   // 128 x 100-stride fp32 region (51.2 KB <= stage 0)
    if (half == 1) {
#pragma unroll
        for (int mt = 0; mt < 2; mt++) {
            int r = row_base + mt * 16 + (lane >> 2);
#pragma unroll
            for (int nt = 0; nt < 6; nt++) {
                int c = col_base + nt * 8 + (lane & 3) * 2;
                *(float2*)(red + r * A_STRIDE + c) =
                    make_float2(acc[mt][nt][0], acc[mt][nt][1]);
                *(float2*)(red + (r + 8) * A_STRIDE + c) =
                    make_float2(acc[mt][nt][2], acc[mt][nt][3]);
            }
        }
    }
    __syncthreads();

    // ---- epilogue (half-0 warps): add partial, bias (+ residual), PReLU, store ----
    if (half == 0) {
        const float a = alpha[0];
#pragma unroll
        for (int mt = 0; mt < 2; mt++) {
            int rl = row_base + mt * 16 + (lane >> 2);
            int r0 = tb + rl;
#pragma unroll
            for (int nt = 0; nt < 6; nt++) {
                int c0 = col_base + nt * 8 + (lane & 3) * 2;
                float2 p0 = *(float2*)(red + rl * A_STRIDE + c0);
                float2 p1 = *(float2*)(red + (rl + 8) * A_STRIDE + c0);
                float b0 = bias[c0], b1 = bias[c0 + 1];
                float v0 = acc[mt][nt][0] + p0.x + b0;
                float v1 = acc[mt][nt][1] + p0.y + b1;
                float v2 = acc[mt][nt][2] + p1.x + b0;
                float v3 = acc[mt][nt][3] + p1.y + b1;
                if (residual) {
                    v0 += residual[(size_t)r0 * CHANS + c0];
                    v1 += residual[(size_t)r0 * CHANS + c0 + 1];
                    v2 += residual[(size_t)(r0 + 8) * CHANS + c0];
                    v3 += residual[(size_t)(r0 + 8) * CHANS + c0 + 1];
                }
                v0 = v0 > 0.f ? v0 : a * v0;
                v1 = v1 > 0.f ? v1 : a * v1;
                v2 = v2 > 0.f ? v2 : a * v2;
                v3 = v3 > 0.f ? v3 : a * v3;
                *(float2*)(out + (size_t)r0 * CHANS + c0)       = make_float2(v0, v1);
                *(float2*)(out + (size_t)(r0 + 8) * CHANS + c0) = make_float2(v2, v3);
            }
        }
    }
}

static const int SMEM_BYTES = STAGE_WORDS * 2 * 4 + 16;   // stages + 2 mbarriers

extern "C" void kernel_launch(void* const* d_in, const int* in_sizes, int n_in,
                              void* d_out, int out_size) {
    const float* feats = (const float*)d_in[0];
    const int*   nbr   = (const int*)d_in[1];
    const int*   msk   = (const int*)d_in[2];   // bool promoted to int32 on the wire
    const float* W1    = (const float*)d_in[3];
    const float* b1    = (const float*)d_in[4];
    const float* a1    = (const float*)d_in[5];
    const float* W2    = (const float*)d_in[6];
    const float* b2    = (const float*)d_in[7];
    const float* a2    = (const float*)d_in[8];
    float*       out   = (float*)d_out;

    float* xbuf = nullptr;
    cudaGetSymbolAddress((void**)&xbuf, g_x);
    float* wpad = nullptr;
    cudaGetSymbolAddress((void**)&wpad, g_Wpad);

    cudaFuncSetAttribute(sparse_conv_kernel,
                         cudaFuncAttributeMaxDynamicSharedMemorySize, SMEM_BYTES);

    // prep: repack both weight tensors into padded layout (cheap, ~2.2MB writes)
    const int prep_n = KOFF * W_TILE_WORDS;
    pad_w_kernel<<<(prep_n + 511) / 512, 512>>>(W1, 0);
    pad_w_kernel<<<(prep_n + 511) / 512, 512>>>(W2, 1);

    dim3 grid(N_PTS / TILE_M);
    // layer 1: x = prelu(conv(feats, W1) + b1)
    sparse_conv_kernel<<<grid, THREADS, SMEM_BYTES>>>(
        feats, nbr, msk, wpad, b1, a1, /*residual=*/nullptr, xbuf);
    // layer 2: out = prelu(conv(x, W2) + b2 + feats)
    sparse_conv_kernel<<<grid, THREADS, SMEM_BYTES>>>(
        xbuf, nbr, msk, wpad + (size_t)KOFF * W_TILE_WORDS, b2, a2,
        /*residual=*/feats, out);
}